// round 10
// baseline (speedup 1.0000x reference)
#include <cuda_runtime.h>
#include <cuda_bf16.h>
#include <cstdint>

// SVDAlign, 3-kernel pipeline:
//  K1: 2 batches/CTA. One TMA load (20800B) -> per-batch 16 moments via folded
//      warp reduce (4 warps per batch) -> g_mom; compact xyz2 -> one TMA store.
//  K2: one THREAD per batch: 3x3 SVD + Kabsch -> g_Rt.         (PDL)
//  K3: elementwise: one thread per point, no barriers/SMEM.    (PDL)

#define NPTS   200
#define NFEAT  13
#define ROW_FLOATS (NPTS * NFEAT)          // 2600
#define ROW_BYTES  (ROW_FLOATS * 4)        // 10400
#define OUT_FLOATS (NPTS * 3)              // 600
#define OUT_BYTES  (OUT_FLOATS * 4)        // 2400
#define MAXB   8192

__device__ __align__(16) float g_mom[MAXB * 16];
__device__ __align__(16) float g_Rt[MAXB * 12];

// ---------------- PTX helpers ----------------
__device__ __forceinline__ uint32_t smem_u32(const void* p) {
    return (uint32_t)__cvta_generic_to_shared(p);
}
__device__ __forceinline__ void mbar_init(uint32_t mbar, uint32_t cnt) {
    asm volatile("mbarrier.init.shared.b64 [%0], %1;" :: "r"(mbar), "r"(cnt) : "memory");
}
__device__ __forceinline__ void mbar_expect_tx(uint32_t mbar, uint32_t bytes) {
    asm volatile("mbarrier.arrive.expect_tx.shared.b64 _, [%0], %1;"
                 :: "r"(mbar), "r"(bytes) : "memory");
}
__device__ __forceinline__ void bulk_g2s(uint32_t dst, const void* src, uint32_t bytes, uint32_t mbar) {
    asm volatile("cp.async.bulk.shared::cluster.global.mbarrier::complete_tx::bytes "
                 "[%0], [%1], %2, [%3];"
                 :: "r"(dst), "l"(src), "r"(bytes), "r"(mbar) : "memory");
}
__device__ __forceinline__ void mbar_wait(uint32_t mbar, uint32_t parity) {
    asm volatile(
        "{\n\t"
        ".reg .pred P;\n\t"
        "WAIT_%=:\n\t"
        "mbarrier.try_wait.parity.shared.b64 P, [%0], %1;\n\t"
        "@P bra DONE_%=;\n\t"
        "bra WAIT_%=;\n\t"
        "DONE_%=:\n\t"
        "}"
        :: "r"(mbar), "r"(parity) : "memory");
}
__device__ __forceinline__ void bulk_s2g(void* dst, uint32_t src, uint32_t bytes) {
    asm volatile("fence.proxy.async.shared::cta;" ::: "memory");
    asm volatile("cp.async.bulk.global.shared::cta.bulk_group [%0], [%1], %2;"
                 :: "l"(dst), "r"(src), "r"(bytes) : "memory");
    asm volatile("cp.async.bulk.commit_group;" ::: "memory");
    asm volatile("cp.async.bulk.wait_group 0;" ::: "memory");
}

// ---------------------------------------------------------------- K1
// 256 threads: threads 0..127 process local batch 0, 128..255 local batch 1.
__global__ __launch_bounds__(256)
void moments_kernel(const float* __restrict__ gin,
                    const float* __restrict__ shift_p,
                    const float* __restrict__ a_p,
                    const float* __restrict__ b_p,
                    float* __restrict__ gout)
{
    __shared__ __align__(16) float sdata[2 * ROW_FLOATS];   // 20800 B
    __shared__ __align__(16) float sout[2 * OUT_FLOATS];    // 4800 B
    __shared__ float sred[2][4][16];
    __shared__ __align__(8) unsigned long long mbar_s;

    const int cta = blockIdx.x;
    const int tid = threadIdx.x;
    const int h   = tid >> 7;          // local batch 0/1
    const int lt  = tid & 127;         // thread within batch group
    const uint32_t mbar = smem_u32(&mbar_s);

    if (tid == 0) mbar_init(mbar, 1);
    __syncthreads();
    if (tid == 0) {
        mbar_expect_tx(mbar, 2 * ROW_BYTES);
        bulk_g2s(smem_u32(sdata), gin + (size_t)cta * 2 * ROW_FLOATS,
                 2 * ROW_BYTES, mbar);
    }

    const float a_s   = __ldg(a_p);
    const float b_s   = __ldg(b_p);
    const float shift = __ldg(shift_p);

    mbar_wait(mbar, 0);

    float acc[16];
    #pragma unroll
    for (int k = 0; k < 16; ++k) acc[k] = 0.0f;

    const float* base = sdata + h * ROW_FLOATS;
    float* obase = sout + h * OUT_FLOATS;

    #pragma unroll
    for (int half_pt = 0; half_pt < 2; ++half_pt) {
        const int pt = lt + half_pt * 128;
        if (pt < NPTS) {
            const float* p = base + pt * NFEAT;
            float w = fmaxf(a_s * p[0] + b_s, 0.0f) + 1e-8f;
            float v1[3], v2[3], x2[3];
            #pragma unroll
            for (int i = 0; i < 3; ++i) {
                v1[i] = p[1 + i] + shift * p[7 + i];
                x2[i] = p[4 + i];
                v2[i] = x2[i] + shift * p[10 + i];
            }
            acc[0] += w;
            #pragma unroll
            for (int i = 0; i < 3; ++i) {
                acc[1 + i] += w * v1[i];
                acc[4 + i] += w * v2[i];
            }
            #pragma unroll
            for (int i = 0; i < 3; ++i)
                #pragma unroll
                for (int j = 0; j < 3; ++j)
                    acc[7 + 3 * i + j] += w * v2[i] * v1[j];

            obase[pt * 3 + 0] = x2[0];
            obase[pt * 3 + 1] = x2[1];
            obase[pt * 3 + 2] = x2[2];
        }
    }

    // ---- folded warp reduction: lane l ends with moment (l & 15) ----
    const int lane = tid & 31;
    const int wib  = (tid >> 5) & 3;   // warp index within batch group (0..3)

    #pragma unroll
    for (int k = 0; k < 16; ++k)
        acc[k] += __shfl_xor_sync(0xffffffffu, acc[k], 16);

    #pragma unroll
    for (int half = 8; half >= 1; half >>= 1) {
        const bool hi = (lane & half) != 0;
        #pragma unroll
        for (int k = 0; k < half; ++k) {
            float send = hi ? acc[k] : acc[k + half];
            float recv = __shfl_xor_sync(0xffffffffu, send, half);
            acc[k] = (hi ? acc[k + half] : acc[k]) + recv;
        }
    }

    if (lane < 16) sred[h][wib][lane] = acc[0];
    __syncthreads();

    // cross-warp: warp 0 finishes batch 0, warp 1 finishes batch 1
    const int warp = tid >> 5;
    if (warp < 2 && lane < 16) {
        float s = sred[warp][0][lane] + sred[warp][1][lane]
                + sred[warp][2][lane] + sred[warp][3][lane];
        g_mom[(cta * 2 + warp) * 16 + lane] = s;
    }

    if (tid == 0) {
        bulk_s2g(gout + (size_t)cta * 2 * OUT_FLOATS, smem_u32(sout), 2 * OUT_BYTES);
    }
}

// ---------------------------------------------------------------- K2
__global__ __launch_bounds__(128)
void svd_kernel(int nbatch)
{
    cudaGridDependencySynchronize();   // PDL: wait for K1's g_mom

    const int b = blockIdx.x * blockDim.x + threadIdx.x;
    if (b >= nbatch) return;

    float m[16];
    {
        const float4* src = reinterpret_cast<const float4*>(g_mom + b * 16);
        #pragma unroll
        for (int i = 0; i < 4; ++i) {
            float4 v = src[i];
            m[4 * i + 0] = v.x; m[4 * i + 1] = v.y;
            m[4 * i + 2] = v.z; m[4 * i + 3] = v.w;
        }
    }

    const float inv = 1.0f / m[0];
    float c1[3], c2[3];
    #pragma unroll
    for (int i = 0; i < 3; ++i) { c1[i] = m[1 + i] * inv; c2[i] = m[4 + i] * inv; }

    float A[3][3];
    #pragma unroll
    for (int i = 0; i < 3; ++i)
        #pragma unroll
        for (int j = 0; j < 3; ++j)
            A[i][j] = m[7 + 3 * i + j] - c2[i] * m[1 + j];

    float S[3][3];
    #pragma unroll
    for (int j = 0; j < 3; ++j)
        #pragma unroll
        for (int k = 0; k < 3; ++k)
            S[j][k] = A[0][j] * A[0][k] + A[1][j] * A[1][k] + A[2][j] * A[2][k];

    float V[3][3] = {{1.f,0.f,0.f},{0.f,1.f,0.f},{0.f,0.f,1.f}};

    #pragma unroll
    for (int sweep = 0; sweep < 6; ++sweep) {
        #pragma unroll
        for (int idx = 0; idx < 3; ++idx) {
            const int p = (idx == 2) ? 1 : 0;
            const int q = (idx == 0) ? 1 : 2;
            float apq = S[p][q];
            if (fabsf(apq) > 1e-20f) {
                float theta = 0.5f * (S[q][q] - S[p][p]) / apq;
                float tt = 1.0f / (fabsf(theta) + sqrtf(theta * theta + 1.0f));
                if (theta < 0.0f) tt = -tt;
                float c = rsqrtf(tt * tt + 1.0f);
                float sn = tt * c;
                #pragma unroll
                for (int k = 0; k < 3; ++k) {
                    float skp = S[k][p], skq = S[k][q];
                    S[k][p] = c * skp - sn * skq;
                    S[k][q] = sn * skp + c * skq;
                }
                #pragma unroll
                for (int k = 0; k < 3; ++k) {
                    float spk = S[p][k], sqk = S[q][k];
                    S[p][k] = c * spk - sn * sqk;
                    S[q][k] = sn * spk + c * sqk;
                }
                #pragma unroll
                for (int k = 0; k < 3; ++k) {
                    float vkp = V[k][p], vkq = V[k][q];
                    V[k][p] = c * vkp - sn * vkq;
                    V[k][q] = sn * vkp + c * vkq;
                }
            }
        }
    }

    float e0 = S[0][0], e1 = S[1][1], e2 = S[2][2];
    #define SWAP_COL(ci, cj, ei, ej) {                                   \
        float te = ei; ei = ej; ej = te;                                  \
        float tv;                                                         \
        tv = V[0][ci]; V[0][ci] = V[0][cj]; V[0][cj] = tv;                \
        tv = V[1][ci]; V[1][ci] = V[1][cj]; V[1][cj] = tv;                \
        tv = V[2][ci]; V[2][ci] = V[2][cj]; V[2][cj] = tv; }
    if (e1 > e0) { SWAP_COL(0, 1, e0, e1) }
    if (e2 > e0) { SWAP_COL(0, 2, e0, e2) }
    if (e2 > e1) { SWAP_COL(1, 2, e1, e2) }
    #undef SWAP_COL

    float U[3][3];
    float sv[3];
    #pragma unroll
    for (int k = 0; k < 3; ++k) {
        float b0 = A[0][0] * V[0][k] + A[0][1] * V[1][k] + A[0][2] * V[2][k];
        float b1 = A[1][0] * V[0][k] + A[1][1] * V[1][k] + A[1][2] * V[2][k];
        float b2 = A[2][0] * V[0][k] + A[2][1] * V[1][k] + A[2][2] * V[2][k];
        float n2 = b0 * b0 + b1 * b1 + b2 * b2;
        sv[k] = sqrtf(fmaxf(n2, 0.0f));
        float invs = (sv[k] > 1e-20f) ? (1.0f / sv[k]) : 0.0f;
        U[0][k] = b0 * invs; U[1][k] = b1 * invs; U[2][k] = b2 * invs;
    }
    if (sv[2] <= 1e-9f * sv[0]) {
        U[0][2] = U[1][0] * U[2][1] - U[2][0] * U[1][1];
        U[1][2] = U[2][0] * U[0][1] - U[0][0] * U[2][1];
        U[2][2] = U[0][0] * U[1][1] - U[1][0] * U[0][1];
    }

    float detV = V[0][0] * (V[1][1] * V[2][2] - V[1][2] * V[2][1])
               - V[0][1] * (V[1][0] * V[2][2] - V[1][2] * V[2][0])
               + V[0][2] * (V[1][0] * V[2][1] - V[1][1] * V[2][0]);
    float detU = U[0][0] * (U[1][1] * U[2][2] - U[1][2] * U[2][1])
               - U[0][1] * (U[1][0] * U[2][2] - U[1][2] * U[2][0])
               + U[0][2] * (U[1][0] * U[2][1] - U[1][1] * U[2][0]);
    float d = (detV * detU < 0.0f) ? -1.0f : 1.0f;

    float R[3][3];
    #pragma unroll
    for (int i = 0; i < 3; ++i)
        #pragma unroll
        for (int j = 0; j < 3; ++j)
            R[i][j] = V[i][0] * U[j][0] + V[i][1] * U[j][1] + d * V[i][2] * U[j][2];

    float* out = g_Rt + b * 12;
    #pragma unroll
    for (int i = 0; i < 3; ++i) {
        #pragma unroll
        for (int j = 0; j < 3; ++j) out[3 * i + j] = R[i][j];
        out[9 + i] = c1[i] - (R[i][0] * c2[0] + R[i][1] * c2[1] + R[i][2] * c2[2]);
    }
}

// ---------------------------------------------------------------- K3
__global__ __launch_bounds__(256)
void apply_points_kernel(float* __restrict__ gout, int npoints)
{
    cudaGridDependencySynchronize();   // PDL: wait for K2's g_Rt

    const int pt = blockIdx.x * blockDim.x + threadIdx.x;
    if (pt >= npoints) return;

    const int b = pt / NPTS;
    const float4* rt4 = reinterpret_cast<const float4*>(g_Rt + b * 12);
    float4 r0 = rt4[0];            // R00 R01 R02 R10
    float4 r1 = rt4[1];            // R11 R12 R20 R21
    float4 r2 = rt4[2];            // R22 t0  t1  t2

    float* p = gout + (size_t)pt * 3;
    float x = p[0], y = p[1], z = p[2];
    float o0 = r0.x * x + r0.y * y + r0.z * z + r2.y;
    float o1 = r0.w * x + r1.x * y + r1.y * z + r2.z;
    float o2 = r1.z * x + r1.w * y + r2.x * z + r2.w;
    p[0] = o0; p[1] = o1; p[2] = o2;
}

extern "C" void kernel_launch(void* const* d_in, const int* in_sizes, int n_in,
                              void* d_out, int out_size)
{
    const float* net   = (const float*)d_in[0];
    const float* shift = (const float*)d_in[1];
    const float* a     = (const float*)d_in[2];
    const float* b     = (const float*)d_in[3];
    float* out = (float*)d_out;

    int nbatch  = in_sizes[0] / ROW_FLOATS;   // 8192
    int npoints = nbatch * NPTS;              // 1,638,400

    moments_kernel<<<nbatch / 2, 256>>>(net, shift, a, b, out);

    // PDL launches: dependent grids go resident while the producer drains.
    cudaLaunchAttribute attr[1];
    attr[0].id = cudaLaunchAttributeProgrammaticStreamSerialization;
    attr[0].val.programmaticStreamSerializationAllowed = 1;

    {
        cudaLaunchConfig_t cfg = {};
        cfg.gridDim  = dim3((nbatch + 127) / 128);
        cfg.blockDim = dim3(128);
        cfg.attrs = attr;
        cfg.numAttrs = 1;
        cudaLaunchKernelEx(&cfg, svd_kernel, nbatch);
    }
    {
        cudaLaunchConfig_t cfg = {};
        cfg.gridDim  = dim3((npoints + 255) / 256);
        cfg.blockDim = dim3(256);
        cfg.attrs = attr;
        cfg.numAttrs = 1;
        cudaLaunchKernelEx(&cfg, apply_points_kernel, out, npoints);
    }
}

// round 12
// speedup vs baseline: 1.0999x; 1.0999x over previous
#include <cuda_runtime.h>
#include <cuda_bf16.h>
#include <cstdint>

// SVDAlign, 3-kernel pipeline (R9 K1 + PDL tail):
//  K1: 1 batch/CTA, 128 thr: TMA row load -> 16 moments via folded warp
//      reduce -> g_mom; compact xyz2 -> TMA store into d_out.  (proven 17.9us)
//  K2: one THREAD per batch: 3x3 SVD + Kabsch -> g_Rt.         (PDL)
//  K3: elementwise: one thread per point, no barriers/SMEM.    (PDL)

#define NPTS   200
#define NFEAT  13
#define ROW_FLOATS (NPTS * NFEAT)          // 2600
#define ROW_BYTES  (ROW_FLOATS * 4)        // 10400
#define OUT_FLOATS (NPTS * 3)              // 600
#define OUT_BYTES  (OUT_FLOATS * 4)        // 2400
#define MAXB   8192

__device__ __align__(16) float g_mom[MAXB * 16];
__device__ __align__(16) float g_Rt[MAXB * 12];

// ---------------- PTX helpers ----------------
__device__ __forceinline__ uint32_t smem_u32(const void* p) {
    return (uint32_t)__cvta_generic_to_shared(p);
}
__device__ __forceinline__ void mbar_init(uint32_t mbar, uint32_t cnt) {
    asm volatile("mbarrier.init.shared.b64 [%0], %1;" :: "r"(mbar), "r"(cnt) : "memory");
}
__device__ __forceinline__ void mbar_expect_tx(uint32_t mbar, uint32_t bytes) {
    asm volatile("mbarrier.arrive.expect_tx.shared.b64 _, [%0], %1;"
                 :: "r"(mbar), "r"(bytes) : "memory");
}
__device__ __forceinline__ void bulk_g2s(uint32_t dst, const void* src, uint32_t bytes, uint32_t mbar) {
    asm volatile("cp.async.bulk.shared::cluster.global.mbarrier::complete_tx::bytes "
                 "[%0], [%1], %2, [%3];"
                 :: "r"(dst), "l"(src), "r"(bytes), "r"(mbar) : "memory");
}
__device__ __forceinline__ void mbar_wait(uint32_t mbar, uint32_t parity) {
    asm volatile(
        "{\n\t"
        ".reg .pred P;\n\t"
        "WAIT_%=:\n\t"
        "mbarrier.try_wait.parity.shared.b64 P, [%0], %1;\n\t"
        "@P bra DONE_%=;\n\t"
        "bra WAIT_%=;\n\t"
        "DONE_%=:\n\t"
        "}"
        :: "r"(mbar), "r"(parity) : "memory");
}
__device__ __forceinline__ void bulk_s2g(void* dst, uint32_t src, uint32_t bytes) {
    asm volatile("fence.proxy.async.shared::cta;" ::: "memory");
    asm volatile("cp.async.bulk.global.shared::cta.bulk_group [%0], [%1], %2;"
                 :: "l"(dst), "r"(src), "r"(bytes) : "memory");
    asm volatile("cp.async.bulk.commit_group;" ::: "memory");
    asm volatile("cp.async.bulk.wait_group 0;" ::: "memory");
}

// ---------------------------------------------------------------- K1
__global__ __launch_bounds__(128)
void moments_kernel(const float* __restrict__ gin,
                    const float* __restrict__ shift_p,
                    const float* __restrict__ a_p,
                    const float* __restrict__ b_p,
                    float* __restrict__ gout)
{
    __shared__ __align__(16) float sdata[ROW_FLOATS];   // 10400 B
    __shared__ __align__(16) float sout[OUT_FLOATS];    // 2400 B compacted xyz2
    __shared__ float sred[4][16];
    __shared__ __align__(8) unsigned long long mbar_s;

    const int bid = blockIdx.x;
    const int tid = threadIdx.x;
    const uint32_t mbar = smem_u32(&mbar_s);

    if (tid == 0) mbar_init(mbar, 1);
    __syncthreads();
    if (tid == 0) {
        mbar_expect_tx(mbar, ROW_BYTES);
        bulk_g2s(smem_u32(sdata), gin + (size_t)bid * ROW_FLOATS, ROW_BYTES, mbar);
    }

    const float a_s   = __ldg(a_p);
    const float b_s   = __ldg(b_p);
    const float shift = __ldg(shift_p);

    mbar_wait(mbar, 0);

    float acc[16];
    #pragma unroll
    for (int k = 0; k < 16; ++k) acc[k] = 0.0f;

    #pragma unroll
    for (int half_pt = 0; half_pt < 2; ++half_pt) {
        const int pt = tid + half_pt * 128;
        if (pt < NPTS) {
            const float* p = sdata + pt * NFEAT;
            float w = fmaxf(a_s * p[0] + b_s, 0.0f) + 1e-8f;
            float v1[3], v2[3], x2[3];
            #pragma unroll
            for (int i = 0; i < 3; ++i) {
                v1[i] = p[1 + i] + shift * p[7 + i];
                x2[i] = p[4 + i];
                v2[i] = x2[i] + shift * p[10 + i];
            }
            acc[0] += w;
            #pragma unroll
            for (int i = 0; i < 3; ++i) {
                acc[1 + i] += w * v1[i];
                acc[4 + i] += w * v2[i];
            }
            #pragma unroll
            for (int i = 0; i < 3; ++i)
                #pragma unroll
                for (int j = 0; j < 3; ++j)
                    acc[7 + 3 * i + j] += w * v2[i] * v1[j];

            sout[pt * 3 + 0] = x2[0];
            sout[pt * 3 + 1] = x2[1];
            sout[pt * 3 + 2] = x2[2];
        }
    }

    // ---- folded warp reduction: lane l ends with moment (l & 15) ----
    const int lane = tid & 31;
    const int warp = tid >> 5;

    #pragma unroll
    for (int k = 0; k < 16; ++k)
        acc[k] += __shfl_xor_sync(0xffffffffu, acc[k], 16);

    #pragma unroll
    for (int half = 8; half >= 1; half >>= 1) {
        const bool hi = (lane & half) != 0;
        #pragma unroll
        for (int k = 0; k < half; ++k) {
            float send = hi ? acc[k] : acc[k + half];
            float recv = __shfl_xor_sync(0xffffffffu, send, half);
            acc[k] = (hi ? acc[k + half] : acc[k]) + recv;
        }
    }

    if (lane < 16) sred[warp][lane] = acc[0];
    __syncthreads();

    if (tid < 16) {
        float s = sred[0][tid] + sred[1][tid] + sred[2][tid] + sred[3][tid];
        g_mom[bid * 16 + tid] = s;
    }
    if (tid == 0) {
        bulk_s2g(gout + (size_t)bid * OUT_FLOATS, smem_u32(sout), OUT_BYTES);
    }
}

// ---------------------------------------------------------------- K2
__global__ __launch_bounds__(128)
void svd_kernel(int nbatch)
{
    cudaGridDependencySynchronize();   // PDL: wait for K1's g_mom

    const int b = blockIdx.x * blockDim.x + threadIdx.x;
    if (b >= nbatch) return;

    float m[16];
    {
        const float4* src = reinterpret_cast<const float4*>(g_mom + b * 16);
        #pragma unroll
        for (int i = 0; i < 4; ++i) {
            float4 v = src[i];
            m[4 * i + 0] = v.x; m[4 * i + 1] = v.y;
            m[4 * i + 2] = v.z; m[4 * i + 3] = v.w;
        }
    }

    const float inv = 1.0f / m[0];
    float c1[3], c2[3];
    #pragma unroll
    for (int i = 0; i < 3; ++i) { c1[i] = m[1 + i] * inv; c2[i] = m[4 + i] * inv; }

    float A[3][3];
    #pragma unroll
    for (int i = 0; i < 3; ++i)
        #pragma unroll
        for (int j = 0; j < 3; ++j)
            A[i][j] = m[7 + 3 * i + j] - c2[i] * m[1 + j];

    float S[3][3];
    #pragma unroll
    for (int j = 0; j < 3; ++j)
        #pragma unroll
        for (int k = 0; k < 3; ++k)
            S[j][k] = A[0][j] * A[0][k] + A[1][j] * A[1][k] + A[2][j] * A[2][k];

    float V[3][3] = {{1.f,0.f,0.f},{0.f,1.f,0.f},{0.f,0.f,1.f}};

    #pragma unroll
    for (int sweep = 0; sweep < 6; ++sweep) {
        #pragma unroll
        for (int idx = 0; idx < 3; ++idx) {
            const int p = (idx == 2) ? 1 : 0;
            const int q = (idx == 0) ? 1 : 2;
            float apq = S[p][q];
            if (fabsf(apq) > 1e-20f) {
                float theta = 0.5f * (S[q][q] - S[p][p]) / apq;
                float tt = 1.0f / (fabsf(theta) + sqrtf(theta * theta + 1.0f));
                if (theta < 0.0f) tt = -tt;
                float c = rsqrtf(tt * tt + 1.0f);
                float sn = tt * c;
                #pragma unroll
                for (int k = 0; k < 3; ++k) {
                    float skp = S[k][p], skq = S[k][q];
                    S[k][p] = c * skp - sn * skq;
                    S[k][q] = sn * skp + c * skq;
                }
                #pragma unroll
                for (int k = 0; k < 3; ++k) {
                    float spk = S[p][k], sqk = S[q][k];
                    S[p][k] = c * spk - sn * sqk;
                    S[q][k] = sn * spk + c * sqk;
                }
                #pragma unroll
                for (int k = 0; k < 3; ++k) {
                    float vkp = V[k][p], vkq = V[k][q];
                    V[k][p] = c * vkp - sn * vkq;
                    V[k][q] = sn * vkp + c * vkq;
                }
            }
        }
    }

    float e0 = S[0][0], e1 = S[1][1], e2 = S[2][2];
    #define SWAP_COL(ci, cj, ei, ej) {                                   \
        float te = ei; ei = ej; ej = te;                                  \
        float tv;                                                         \
        tv = V[0][ci]; V[0][ci] = V[0][cj]; V[0][cj] = tv;                \
        tv = V[1][ci]; V[1][ci] = V[1][cj]; V[1][cj] = tv;                \
        tv = V[2][ci]; V[2][ci] = V[2][cj]; V[2][cj] = tv; }
    if (e1 > e0) { SWAP_COL(0, 1, e0, e1) }
    if (e2 > e0) { SWAP_COL(0, 2, e0, e2) }
    if (e2 > e1) { SWAP_COL(1, 2, e1, e2) }
    #undef SWAP_COL

    float U[3][3];
    float sv[3];
    #pragma unroll
    for (int k = 0; k < 3; ++k) {
        float b0 = A[0][0] * V[0][k] + A[0][1] * V[1][k] + A[0][2] * V[2][k];
        float b1 = A[1][0] * V[0][k] + A[1][1] * V[1][k] + A[1][2] * V[2][k];
        float b2 = A[2][0] * V[0][k] + A[2][1] * V[1][k] + A[2][2] * V[2][k];
        float n2 = b0 * b0 + b1 * b1 + b2 * b2;
        sv[k] = sqrtf(fmaxf(n2, 0.0f));
        float invs = (sv[k] > 1e-20f) ? (1.0f / sv[k]) : 0.0f;
        U[0][k] = b0 * invs; U[1][k] = b1 * invs; U[2][k] = b2 * invs;
    }
    if (sv[2] <= 1e-9f * sv[0]) {
        U[0][2] = U[1][0] * U[2][1] - U[2][0] * U[1][1];
        U[1][2] = U[2][0] * U[0][1] - U[0][0] * U[2][1];
        U[2][2] = U[0][0] * U[1][1] - U[1][0] * U[0][1];
    }

    float detV = V[0][0] * (V[1][1] * V[2][2] - V[1][2] * V[2][1])
               - V[0][1] * (V[1][0] * V[2][2] - V[1][2] * V[2][0])
               + V[0][2] * (V[1][0] * V[2][1] - V[1][1] * V[2][0]);
    float detU = U[0][0] * (U[1][1] * U[2][2] - U[1][2] * U[2][1])
               - U[0][1] * (U[1][0] * U[2][2] - U[1][2] * U[2][0])
               + U[0][2] * (U[1][0] * U[2][1] - U[1][1] * U[2][0]);
    float d = (detV * detU < 0.0f) ? -1.0f : 1.0f;

    float R[3][3];
    #pragma unroll
    for (int i = 0; i < 3; ++i)
        #pragma unroll
        for (int j = 0; j < 3; ++j)
            R[i][j] = V[i][0] * U[j][0] + V[i][1] * U[j][1] + d * V[i][2] * U[j][2];

    float* out = g_Rt + b * 12;
    #pragma unroll
    for (int i = 0; i < 3; ++i) {
        #pragma unroll
        for (int j = 0; j < 3; ++j) out[3 * i + j] = R[i][j];
        out[9 + i] = c1[i] - (R[i][0] * c2[0] + R[i][1] * c2[1] + R[i][2] * c2[2]);
    }
}

// ---------------------------------------------------------------- K3
__global__ __launch_bounds__(256)
void apply_points_kernel(float* __restrict__ gout, int npoints)
{
    cudaGridDependencySynchronize();   // PDL: wait for K2's g_Rt

    const int pt = blockIdx.x * blockDim.x + threadIdx.x;
    if (pt >= npoints) return;

    const int b = pt / NPTS;
    const float4* rt4 = reinterpret_cast<const float4*>(g_Rt + b * 12);
    float4 r0 = rt4[0];            // R00 R01 R02 R10
    float4 r1 = rt4[1];            // R11 R12 R20 R21
    float4 r2 = rt4[2];            // R22 t0  t1  t2

    float* p = gout + (size_t)pt * 3;
    float x = p[0], y = p[1], z = p[2];
    float o0 = r0.x * x + r0.y * y + r0.z * z + r2.y;
    float o1 = r0.w * x + r1.x * y + r1.y * z + r2.z;
    float o2 = r1.z * x + r1.w * y + r2.x * z + r2.w;
    p[0] = o0; p[1] = o1; p[2] = o2;
}

extern "C" void kernel_launch(void* const* d_in, const int* in_sizes, int n_in,
                              void* d_out, int out_size)
{
    const float* net   = (const float*)d_in[0];
    const float* shift = (const float*)d_in[1];
    const float* a     = (const float*)d_in[2];
    const float* b     = (const float*)d_in[3];
    float* out = (float*)d_out;

    int nbatch  = in_sizes[0] / ROW_FLOATS;   // 8192
    int npoints = nbatch * NPTS;              // 1,638,400

    moments_kernel<<<nbatch, 128>>>(net, shift, a, b, out);

    // PDL launches: dependent grids go resident while the producer drains.
    cudaLaunchAttribute attr[1];
    attr[0].id = cudaLaunchAttributeProgrammaticStreamSerialization;
    attr[0].val.programmaticStreamSerializationAllowed = 1;

    {
        cudaLaunchConfig_t cfg = {};
        cfg.gridDim  = dim3((nbatch + 127) / 128);
        cfg.blockDim = dim3(128);
        cfg.attrs = attr;
        cfg.numAttrs = 1;
        cudaLaunchKernelEx(&cfg, svd_kernel, nbatch);
    }
    {
        cudaLaunchConfig_t cfg = {};
        cfg.gridDim  = dim3((npoints + 255) / 256);
        cfg.blockDim = dim3(256);
        cfg.attrs = attr;
        cfg.numAttrs = 1;
        cudaLaunchKernelEx(&cfg, apply_points_kernel, out, npoints);
    }
}